// round 8
// baseline (speedup 1.0000x reference)
#include <cuda_runtime.h>
#include <cuda_bf16.h>
#include <cuda_fp16.h>
#include <cstdint>
#include <math.h>

#define NN   100000
#define EE   1600000
#define HID  128
#define OUTC 64
#define BNEPS 1e-5f

// ---------------- scratch (static device globals; no allocation) ----------------
__device__ int   g_deg[NN];
__device__ int   g_incl[NN];
__device__ int   g_bsum[128];
__device__ int   g_boff[128];
__device__ int   g_rowptr[NN + 1];
__device__ int   g_cursor[NN];
__device__ int   g_col[EE];
__device__ float g_invdeg[NN];
__device__ __half         g_u[(size_t)NN * HID];    // projection to aggregate (fp16)
__device__ float          g_v[(size_t)NN * HID];    // self projection (fp32)
__device__ __nv_bfloat16  g_xhi[(size_t)NN * HID];  // pre-split inputs / activations
__device__ __nv_bfloat16  g_xlo[(size_t)NN * HID];
__device__ __nv_bfloat16  g_hhi[(size_t)NN * HID];
__device__ __nv_bfloat16  g_hlo[(size_t)NN * HID];

// ---------------- CSR build ----------------
__global__ void k_zero_deg() {
    int i = blockIdx.x * blockDim.x + threadIdx.x;
    if (i < NN) g_deg[i] = 0;
}
__global__ void k_count(const int* __restrict__ dst) {
    int e = blockIdx.x * blockDim.x + threadIdx.x;
    if (e < EE) atomicAdd(&g_deg[dst[e]], 1);
}
__global__ void k_scan_block() {
    __shared__ int warpsums[32];
    int i = blockIdx.x * 1024 + threadIdx.x;
    int lane = threadIdx.x & 31, warp = threadIdx.x >> 5;
    int v = (i < NN) ? g_deg[i] : 0;
    int x = v;
    #pragma unroll
    for (int d = 1; d < 32; d <<= 1) { int t = __shfl_up_sync(~0u, x, d); if (lane >= d) x += t; }
    if (lane == 31) warpsums[warp] = x;
    __syncthreads();
    if (threadIdx.x < 32) {
        int w = warpsums[threadIdx.x]; int y = w;
        #pragma unroll
        for (int d = 1; d < 32; d <<= 1) { int t = __shfl_up_sync(~0u, y, d); if (threadIdx.x >= d) y += t; }
        warpsums[threadIdx.x] = y - w;
    }
    __syncthreads();
    x += warpsums[warp];
    if (i < NN) g_incl[i] = x;
    if (threadIdx.x == 1023) g_bsum[blockIdx.x] = x;
}
__global__ void k_scan_tot(int nb) {
    __shared__ int ws[4];
    int t = threadIdx.x, lane = t & 31, warp = t >> 5;
    int v = (t < nb) ? g_bsum[t] : 0;
    int x = v;
    #pragma unroll
    for (int d = 1; d < 32; d <<= 1) { int tt = __shfl_up_sync(~0u, x, d); if (lane >= d) x += tt; }
    if (lane == 31) ws[warp] = x;
    __syncthreads();
    if (t == 0) { int a = 0; for (int j = 0; j < 4; j++) { int tmp = ws[j]; ws[j] = a; a += tmp; } }
    __syncthreads();
    x += ws[warp];
    if (t < nb) g_boff[t] = x - v;
}
__global__ void k_finalize() {
    int i = blockIdx.x * blockDim.x + threadIdx.x;
    if (i < NN) {
        int d = g_deg[i];
        int rp = g_incl[i] + g_boff[i >> 10] - d;
        g_rowptr[i] = rp;
        g_cursor[i] = rp;
        g_invdeg[i] = 1.0f / (float)max(d, 1);
    }
    if (i == 0) g_rowptr[NN] = EE;
}
__global__ void k_fill(const int* __restrict__ src, const int* __restrict__ dst) {
    int e = blockIdx.x * blockDim.x + threadIdx.x;
    if (e < EE) { int p = atomicAdd(&g_cursor[dst[e]], 1); g_col[p] = src[e]; }
}

// ================= helpers =================
__device__ __forceinline__ uint32_t smem_u32(const void* p) {
    uint32_t a;
    asm("{ .reg .u64 t; cvta.to.shared.u64 t, %1; cvt.u32.u64 %0, t; }" : "=r"(a) : "l"(p));
    return a;
}
__device__ __forceinline__ void ldm_x4(uint32_t* r, uint32_t addr) {
    asm volatile("ldmatrix.sync.aligned.m8n8.x4.shared.b16 {%0,%1,%2,%3}, [%4];"
        : "=r"(r[0]), "=r"(r[1]), "=r"(r[2]), "=r"(r[3]) : "r"(addr));
}
__device__ __forceinline__ void mma16816(float* d, const uint32_t* a, const uint32_t* b) {
    asm volatile("mma.sync.aligned.m16n8k16.row.col.f32.bf16.bf16.f32 "
        "{%0,%1,%2,%3}, {%4,%5,%6,%7}, {%8,%9}, {%0,%1,%2,%3};"
        : "+f"(d[0]), "+f"(d[1]), "+f"(d[2]), "+f"(d[3])
        : "r"(a[0]), "r"(a[1]), "r"(a[2]), "r"(a[3]), "r"(b[0]), "r"(b[1]));
}
__device__ __forceinline__ uint32_t bfsplit2(float a, float b, uint32_t& lo) {
    __nv_bfloat16 h0 = __float2bfloat16_rn(a), h1 = __float2bfloat16_rn(b);
    float r0 = a - __bfloat162float(h0), r1 = b - __bfloat162float(h1);
    __nv_bfloat16 l0 = __float2bfloat16_rn(r0), l1 = __float2bfloat16_rn(r1);
    lo = (uint32_t)__bfloat16_as_ushort(l0) | ((uint32_t)__bfloat16_as_ushort(l1) << 16);
    return (uint32_t)__bfloat16_as_ushort(h0) | ((uint32_t)__bfloat16_as_ushort(h1) << 16);
}
// swizzled smem address: row stride 256B (128 bf16), 16B chunks XORed by row&7
__device__ __forceinline__ uint32_t swaddr(uint32_t base, int row, int chunk) {
    return base + (uint32_t)(row * 256) + (uint32_t)(((chunk ^ (row & 7)) << 4));
}
__device__ __forceinline__ void cp16(uint32_t saddr, const void* gptr, int vsz) {
    asm volatile("cp.async.cg.shared.global [%0], [%1], 16, %2;"
        :: "r"(saddr), "l"(gptr), "r"(vsz) : "memory");
}
#define CP_COMMIT() asm volatile("cp.async.commit_group;" ::: "memory")
#define CP_WAIT1()  asm volatile("cp.async.wait_group 1;" ::: "memory")

// ---------------- pre-split x -> bf16 hi/lo ----------------
__global__ void k_split(const float* __restrict__ x,
                        __nv_bfloat16* __restrict__ hi, __nv_bfloat16* __restrict__ lo, int n4) {
    int i = blockIdx.x * blockDim.x + threadIdx.x;
    if (i >= n4) return;
    float4 v = ((const float4*)x)[i];
    uint32_t l01, l23;
    uint32_t h01 = bfsplit2(v.x, v.y, l01);
    uint32_t h23 = bfsplit2(v.z, v.w, l23);
    ((uint2*)hi)[i] = make_uint2(h01, h23);
    ((uint2*)lo)[i] = make_uint2(l01, l23);
}

// ================= double-buffered bf16 split-precision GEMM =================
// out[node][cg] = sum_k A[node][k] * W[cg][k],  W = [Wl;Wr] stacked (NOUT rows).
// A pre-split bf16 hi/lo (row-linear). 64-row tiles, 256 thr, 8 warps (2m x 4n).
// cp.async double buffer hides staging. Cols [0,NH)->uout fp16, [NH,NOUT)->vout fp32.
template <int NOUT>
__global__ void __launch_bounds__(256, 1)
k_mma_gemm(const __nv_bfloat16* __restrict__ Ahi, const __nv_bfloat16* __restrict__ Alo,
           const float* __restrict__ Wl, const float* __restrict__ Wr,
           __half* __restrict__ uout, float* __restrict__ vout)
{
    constexpr int NH = NOUT / 2;
    constexpr int NTILES = (NN + 63) / 64;
    constexpr uint32_t OFF_WH = 0, OFF_WL = 32768, OFF_A = 65536;  // A buf: +b*32768 (hi +0, lo +16384)

    extern __shared__ char sm[];
    uint32_t sb = smem_u32(sm);

    int tid = threadIdx.x;
    int wid = tid >> 5;
    int lane = tid & 31;
    int wm = wid & 1, wn = wid >> 1;
    int by = blockIdx.y;

    // ---- stage weights once (128 cols x 128 k, fp32 -> hi/lo, swizzled) ----
    for (int idx = tid; idx < 128 * 32; idx += 256) {
        int r = idx >> 5, q = idx & 31;
        int gcol = by * 128 + r;
        const float* ws = (gcol < NH) ? (Wl + (size_t)gcol * HID + q * 4)
                                      : (Wr + (size_t)(gcol - NH) * HID + q * 4);
        float4 w = *(const float4*)ws;
        uint32_t l01, l23;
        uint32_t h01 = bfsplit2(w.x, w.y, l01);
        uint32_t h23 = bfsplit2(w.z, w.w, l23);
        uint32_t a = swaddr(sb, r, q >> 1) + (q & 1) * 8;
        *(uint2*)(sm + (a - sb) + OFF_WH) = make_uint2(h01, h23);
        *(uint2*)(sm + (a - sb) + OFF_WL) = make_uint2(l01, l23);
    }

    int lane15 = lane & 15, lhalf = lane >> 4;
    int t4 = lane & 3, g8 = lane >> 2;
    int mrow = wm * 32 + lane15;   // within 64-row tile
    int nrow = wn * 32 + lane15;   // within 128-col W tile

    // stage A tile (64 rows, hi+lo) into buffer b via cp.async
    auto issue_tile = [&](int tile, int b) {
        int nodebase = tile * 64;
        uint32_t abase = sb + OFF_A + (uint32_t)b * 32768;
        for (int i = tid; i < 1024; i += 256) {
            int r = i >> 4, c = i & 15;
            int node = nodebase + r;
            int vsz = (node < NN) ? 16 : 0;
            uint32_t sa = swaddr(abase, r, c);
            cp16(sa,         (const char*)Ahi + (size_t)node * 256 + c * 16, vsz);
            cp16(sa + 16384, (const char*)Alo + (size_t)node * 256 + c * 16, vsz);
        }
    };

    int t0 = blockIdx.x;
    if (t0 < NTILES) issue_tile(t0, 0);
    CP_COMMIT();

    int buf = 0;
    for (int tile = t0; tile < NTILES; tile += gridDim.x) {
        int nxt = tile + gridDim.x;
        if (nxt < NTILES) issue_tile(nxt, buf ^ 1);
        CP_COMMIT();
        CP_WAIT1();
        __syncthreads();

        uint32_t ah_base = sb + OFF_A + (uint32_t)buf * 32768;
        uint32_t al_base = ah_base + 16384;

        float acc[2][4][4];
        #pragma unroll
        for (int i = 0; i < 2; i++)
            #pragma unroll
            for (int j = 0; j < 4; j++)
                #pragma unroll
                for (int e = 0; e < 4; e++) acc[i][j][e] = 0.f;

        #pragma unroll
        for (int ks = 0; ks < 8; ks++) {
            int ch = ks * 2 + lhalf;
            uint32_t Ah[2][4], Al[2][4], Bh[4][2], Bl[4][2], tb[4];
            ldm_x4(Ah[0], swaddr(ah_base, mrow,      ch));
            ldm_x4(Ah[1], swaddr(ah_base, mrow + 16, ch));
            ldm_x4(Al[0], swaddr(al_base, mrow,      ch));
            ldm_x4(Al[1], swaddr(al_base, mrow + 16, ch));
            ldm_x4(tb, swaddr(sb + OFF_WH, nrow, ch));
            Bh[0][0] = tb[0]; Bh[0][1] = tb[2]; Bh[1][0] = tb[1]; Bh[1][1] = tb[3];
            ldm_x4(tb, swaddr(sb + OFF_WH, nrow + 16, ch));
            Bh[2][0] = tb[0]; Bh[2][1] = tb[2]; Bh[3][0] = tb[1]; Bh[3][1] = tb[3];
            ldm_x4(tb, swaddr(sb + OFF_WL, nrow, ch));
            Bl[0][0] = tb[0]; Bl[0][1] = tb[2]; Bl[1][0] = tb[1]; Bl[1][1] = tb[3];
            ldm_x4(tb, swaddr(sb + OFF_WL, nrow + 16, ch));
            Bl[2][0] = tb[0]; Bl[2][1] = tb[2]; Bl[3][0] = tb[1]; Bl[3][1] = tb[3];

            #pragma unroll
            for (int mi = 0; mi < 2; mi++)
                #pragma unroll
                for (int nf = 0; nf < 4; nf++) {
                    mma16816(acc[mi][nf], Ah[mi], Bh[nf]);
                    mma16816(acc[mi][nf], Al[mi], Bh[nf]);
                    mma16816(acc[mi][nf], Ah[mi], Bl[nf]);
                }
        }

        int nodebase = tile * 64;
        #pragma unroll
        for (int mi = 0; mi < 2; mi++) {
            int row0 = nodebase + wm * 32 + mi * 16 + g8;
            #pragma unroll
            for (int nf = 0; nf < 4; nf++) {
                int cg = by * 128 + wn * 32 + nf * 8 + 2 * t4;
                if (cg < NH) {
                    __half* dp = uout + cg;
                    if (row0 < NN)
                        *(half2*)(dp + (size_t)row0 * NH) =
                            __floats2half2_rn(acc[mi][nf][0], acc[mi][nf][1]);
                    if (row0 + 8 < NN)
                        *(half2*)(dp + (size_t)(row0 + 8) * NH) =
                            __floats2half2_rn(acc[mi][nf][2], acc[mi][nf][3]);
                } else {
                    float* dp = vout + (cg - NH);
                    if (row0 < NN)
                        *(float2*)(dp + (size_t)row0 * NH) =
                            make_float2(acc[mi][nf][0], acc[mi][nf][1]);
                    if (row0 + 8 < NN)
                        *(float2*)(dp + (size_t)(row0 + 8) * NH) =
                            make_float2(acc[mi][nf][2], acc[mi][nf][3]);
                }
            }
        }
        __syncthreads();   // all warps done with buf before it is re-staged
        buf ^= 1;
    }
}

// ---------------- fused mean-aggregate + bias + BN + ReLU (layers 1,2) ----------------
// 2 edges/iter: half-warps handle different neighbors, 16B loads; output bf16 hi/lo.
__global__ void k_agg_bn(const __half* __restrict__ u, const float* __restrict__ v,
                         const float* __restrict__ bias, const float* __restrict__ gam,
                         const float* __restrict__ bet, const float* __restrict__ rmean,
                         const float* __restrict__ rvar,
                         __nv_bfloat16* __restrict__ hhi, __nv_bfloat16* __restrict__ hlo)
{
    int gw = (blockIdx.x * blockDim.x + threadIdx.x) >> 5;
    int lane = threadIdx.x & 31;
    if (gw >= NN) return;
    int half = lane >> 4, l15 = lane & 15;
    int s0 = g_rowptr[gw], s1 = g_rowptr[gw + 1];
    const uint4* ub = (const uint4*)u;   // row = 16 uint4 (128 halves)
    float acc[8];
    #pragma unroll
    for (int k = 0; k < 8; k++) acc[k] = 0.f;

    for (int b = s0; b < s1; b += 32) {
        int cnt = s1 - b; if (cnt > 32) cnt = 32;
        int idxv = (lane < cnt) ? g_col[b + lane] : 0;
        int npair = (cnt + 1) >> 1;
        for (int jj = 0; jj < npair; jj++) {
            int j0 = 2 * jj + half;
            int s = __shfl_sync(~0u, idxv, j0);
            float p = (j0 < cnt) ? 1.f : 0.f;
            uint4 t = ub[(size_t)s * 16 + l15];
            float2 f0 = __half22float2(*(const half2*)&t.x);
            float2 f1 = __half22float2(*(const half2*)&t.y);
            float2 f2 = __half22float2(*(const half2*)&t.z);
            float2 f3 = __half22float2(*(const half2*)&t.w);
            acc[0] = fmaf(p, f0.x, acc[0]); acc[1] = fmaf(p, f0.y, acc[1]);
            acc[2] = fmaf(p, f1.x, acc[2]); acc[3] = fmaf(p, f1.y, acc[3]);
            acc[4] = fmaf(p, f2.x, acc[4]); acc[5] = fmaf(p, f2.y, acc[5]);
            acc[6] = fmaf(p, f3.x, acc[6]); acc[7] = fmaf(p, f3.y, acc[7]);
        }
    }
    #pragma unroll
    for (int k = 0; k < 8; k++) acc[k] += __shfl_xor_sync(~0u, acc[k], 16);

    if (half == 0) {
        float iv = g_invdeg[gw];
        int cb = l15 * 8;
        size_t rb = (size_t)gw * HID + cb;
        float4 vv0 = *(const float4*)(v + rb),       vv1 = *(const float4*)(v + rb + 4);
        float4 bb0 = *(const float4*)(bias + cb),    bb1 = *(const float4*)(bias + cb + 4);
        float4 gg0 = *(const float4*)(gam + cb),     gg1 = *(const float4*)(gam + cb + 4);
        float4 be0 = *(const float4*)(bet + cb),     be1 = *(const float4*)(bet + cb + 4);
        float4 rm0 = *(const float4*)(rmean + cb),   rm1 = *(const float4*)(rmean + cb + 4);
        float4 rv0 = *(const float4*)(rvar + cb),    rv1 = *(const float4*)(rvar + cb + 4);
        float o[8];
        o[0] = fmaxf((acc[0] * iv + bb0.x + vv0.x - rm0.x) * (gg0.x * rsqrtf(rv0.x + BNEPS)) + be0.x, 0.f);
        o[1] = fmaxf((acc[1] * iv + bb0.y + vv0.y - rm0.y) * (gg0.y * rsqrtf(rv0.y + BNEPS)) + be0.y, 0.f);
        o[2] = fmaxf((acc[2] * iv + bb0.z + vv0.z - rm0.z) * (gg0.z * rsqrtf(rv0.z + BNEPS)) + be0.z, 0.f);
        o[3] = fmaxf((acc[3] * iv + bb0.w + vv0.w - rm0.w) * (gg0.w * rsqrtf(rv0.w + BNEPS)) + be0.w, 0.f);
        o[4] = fmaxf((acc[4] * iv + bb1.x + vv1.x - rm1.x) * (gg1.x * rsqrtf(rv1.x + BNEPS)) + be1.x, 0.f);
        o[5] = fmaxf((acc[5] * iv + bb1.y + vv1.y - rm1.y) * (gg1.y * rsqrtf(rv1.y + BNEPS)) + be1.y, 0.f);
        o[6] = fmaxf((acc[6] * iv + bb1.z + vv1.z - rm1.z) * (gg1.z * rsqrtf(rv1.z + BNEPS)) + be1.z, 0.f);
        o[7] = fmaxf((acc[7] * iv + bb1.w + vv1.w - rm1.w) * (gg1.w * rsqrtf(rv1.w + BNEPS)) + be1.w, 0.f);
        uint4 hi4, lo4;
        uint32_t* hp = (uint32_t*)&hi4; uint32_t* lp = (uint32_t*)&lo4;
        #pragma unroll
        for (int k = 0; k < 4; k++) hp[k] = bfsplit2(o[2 * k], o[2 * k + 1], lp[k]);
        *(uint4*)((char*)hhi + (size_t)gw * 256 + l15 * 16) = hi4;
        *(uint4*)((char*)hlo + (size_t)gw * 256 + l15 * 16) = lo4;
    }
}

// ---------------- layer 3: mean-aggregate(p fp16, 64-d) + b3 + r, log_softmax ----------------
__global__ void k_agg_lsm(const __half* __restrict__ p, const float* __restrict__ r,
                          const float* __restrict__ b3, float* __restrict__ out)
{
    int gw = (blockIdx.x * blockDim.x + threadIdx.x) >> 5;
    int lane = threadIdx.x & 31;
    if (gw >= NN) return;
    int half = lane >> 4, l15 = lane & 15;
    int s0 = g_rowptr[gw], s1 = g_rowptr[gw + 1];
    const uint2* pb = (const uint2*)p;   // row = 16 uint2 (64 halves)
    float a0 = 0.f, a1 = 0.f, a2 = 0.f, a3 = 0.f;
    for (int b = s0; b < s1; b += 32) {
        int cnt = s1 - b; if (cnt > 32) cnt = 32;
        int idxv = (lane < cnt) ? g_col[b + lane] : 0;
        int npair = (cnt + 1) >> 1;
        for (int jj = 0; jj < npair; jj++) {
            int j0 = 2 * jj + half;
            int s = __shfl_sync(~0u, idxv, j0);
            float pv = (j0 < cnt) ? 1.f : 0.f;
            uint2 t = pb[(size_t)s * 16 + l15];
            float2 f0 = __half22float2(*(const half2*)&t.x);
            float2 f1 = __half22float2(*(const half2*)&t.y);
            a0 = fmaf(pv, f0.x, a0); a1 = fmaf(pv, f0.y, a1);
            a2 = fmaf(pv, f1.x, a2); a3 = fmaf(pv, f1.y, a3);
        }
    }
    a0 += __shfl_xor_sync(~0u, a0, 16);
    a1 += __shfl_xor_sync(~0u, a1, 16);
    a2 += __shfl_xor_sync(~0u, a2, 16);
    a3 += __shfl_xor_sync(~0u, a3, 16);

    float iv = g_invdeg[gw];
    int cb = l15 * 4;
    float4 rr = *(const float4*)(r + (size_t)gw * OUTC + cb);
    float4 bb = *(const float4*)(b3 + cb);
    float l0 = a0 * iv + bb.x + rr.x;
    float l1 = a1 * iv + bb.y + rr.y;
    float l2 = a2 * iv + bb.z + rr.z;
    float l3 = a3 * iv + bb.w + rr.w;
    float m = fmaxf(fmaxf(l0, l1), fmaxf(l2, l3));
    #pragma unroll
    for (int o = 8; o; o >>= 1) m = fmaxf(m, __shfl_xor_sync(~0u, m, o));
    float s = expf(l0 - m) + expf(l1 - m) + expf(l2 - m) + expf(l3 - m);
    #pragma unroll
    for (int o = 8; o; o >>= 1) s += __shfl_xor_sync(~0u, s, o);
    float lse = m + logf(s);
    if (half == 0) {
        float4 o4 = make_float4(l0 - lse, l1 - lse, l2 - lse, l3 - lse);
        *(float4*)(out + (size_t)gw * OUTC + cb) = o4;
    }
}

// ---------------- launch ----------------
extern "C" void kernel_launch(void* const* d_in, const int* in_sizes, int n_in,
                              void* d_out, int out_size)
{
    const float* x   = (const float*)d_in[0];
    const int*   src = (const int*)d_in[1];
    const int*   dst = (const int*)d_in[2];
    const float* W1l = (const float*)d_in[3];
    const float* W1r = (const float*)d_in[4];
    const float* b1  = (const float*)d_in[5];
    const float* g1  = (const float*)d_in[6];
    const float* be1 = (const float*)d_in[7];
    const float* rm1 = (const float*)d_in[8];
    const float* rv1 = (const float*)d_in[9];
    const float* W2l = (const float*)d_in[10];
    const float* W2r = (const float*)d_in[11];
    const float* b2  = (const float*)d_in[12];
    const float* g2  = (const float*)d_in[13];
    const float* be2 = (const float*)d_in[14];
    const float* rm2 = (const float*)d_in[15];
    const float* rv2 = (const float*)d_in[16];
    const float* W3l = (const float*)d_in[17];
    const float* W3r = (const float*)d_in[18];
    const float* b3  = (const float*)d_in[19];
    float* out = (float*)d_out;

    __half* u; float* v;
    __nv_bfloat16 *xhi, *xlo, *hhi, *hlo;
    cudaGetSymbolAddress((void**)&u,   g_u);
    cudaGetSymbolAddress((void**)&v,   g_v);
    cudaGetSymbolAddress((void**)&xhi, g_xhi);
    cudaGetSymbolAddress((void**)&xlo, g_xlo);
    cudaGetSymbolAddress((void**)&hhi, g_hhi);
    cudaGetSymbolAddress((void**)&hlo, g_hlo);

    static cudaStream_t s2 = nullptr;
    static cudaEvent_t ev_fork = nullptr, ev_join = nullptr;
    if (!s2) {
        cudaStreamCreateWithFlags(&s2, cudaStreamNonBlocking);
        cudaEventCreateWithFlags(&ev_fork, cudaEventDisableTiming);
        cudaEventCreateWithFlags(&ev_join, cudaEventDisableTiming);
    }

    const int NB = (NN + 1023) >> 10;
    const int SMEM = 131072;
    cudaFuncSetAttribute(k_mma_gemm<256>, cudaFuncAttributeMaxDynamicSharedMemorySize, SMEM);
    cudaFuncSetAttribute(k_mma_gemm<128>, cudaFuncAttributeMaxDynamicSharedMemorySize, SMEM);

    const int AGG_BLOCKS = (NN * 32 + 255) / 256;

    // ---- fork: CSR build on s2; x split + layer-1 GEMM on main; join before agg ----
    cudaEventRecord(ev_fork, 0);
    cudaStreamWaitEvent(s2, ev_fork, 0);
    k_zero_deg<<<(NN + 255) / 256, 256, 0, s2>>>();
    k_count<<<(EE + 255) / 256, 256, 0, s2>>>(dst);
    k_scan_block<<<NB, 1024, 0, s2>>>();
    k_scan_tot<<<1, 128, 0, s2>>>(NB);
    k_finalize<<<(NN + 255) / 256, 256, 0, s2>>>();
    k_fill<<<(EE + 255) / 256, 256, 0, s2>>>(src, dst);
    cudaEventRecord(ev_join, s2);

    const int N4 = NN * HID / 4;
    k_split<<<(N4 + 255) / 256, 256>>>(x, xhi, xlo, N4);
    // Layer 1 GEMM overlaps CSR build
    k_mma_gemm<256><<<dim3(74, 2), 256, SMEM>>>(xhi, xlo, W1l, W1r, u, v);
    cudaStreamWaitEvent(0, ev_join, 0);
    k_agg_bn<<<AGG_BLOCKS, 256>>>(u, v, b1, g1, be1, rm1, rv1, hhi, hlo);
    // Layer 2
    k_mma_gemm<256><<<dim3(74, 2), 256, SMEM>>>(hhi, hlo, W2l, W2r, u, v);
    k_agg_bn<<<AGG_BLOCKS, 256>>>(u, v, b2, g2, be2, rm2, rv2, hhi, hlo);
    // Layer 3: project h -> [p|r] (64 each), aggregate p, add b3+r, log_softmax
    k_mma_gemm<128><<<dim3(148, 1), 256, SMEM>>>(hhi, hlo, W3l, W3r, u, v);
    k_agg_lsm<<<AGG_BLOCKS, 256>>>(u, v, b3, out);
}

// round 10
// speedup vs baseline: 1.5800x; 1.5800x over previous
#include <cuda_runtime.h>
#include <cuda_bf16.h>
#include <cuda_fp16.h>
#include <cstdint>
#include <math.h>

#define NN   100000
#define EE   1600000
#define HID  128
#define OUTC 64
#define BNEPS 1e-5f

// ---------------- scratch (static device globals; no allocation) ----------------
__device__ int   g_deg[NN];
__device__ int   g_incl[NN];
__device__ int   g_bsum[128];
__device__ int   g_boff[128];
__device__ int   g_rowptr[NN + 1];
__device__ int   g_cursor[NN];
__device__ int   g_col[EE];
__device__ float g_invdeg[NN];
__device__ __half g_u[(size_t)NN * HID];  // projected "left" features (to aggregate), fp16
__device__ float g_v[(size_t)NN * HID];   // projected "right" features (self), fp32
__device__ float g_h[(size_t)NN * HID];   // layer activations

// ---------------- CSR build ----------------
__global__ void k_zero_deg() {
    int i = blockIdx.x * blockDim.x + threadIdx.x;
    if (i < NN) g_deg[i] = 0;
}
__global__ void k_count(const int* __restrict__ dst) {
    int e = blockIdx.x * blockDim.x + threadIdx.x;
    if (e < EE) atomicAdd(&g_deg[dst[e]], 1);
}
__global__ void k_scan_block() {
    __shared__ int warpsums[32];
    int i = blockIdx.x * 1024 + threadIdx.x;
    int lane = threadIdx.x & 31, warp = threadIdx.x >> 5;
    int v = (i < NN) ? g_deg[i] : 0;
    int x = v;
    #pragma unroll
    for (int d = 1; d < 32; d <<= 1) { int t = __shfl_up_sync(~0u, x, d); if (lane >= d) x += t; }
    if (lane == 31) warpsums[warp] = x;
    __syncthreads();
    if (threadIdx.x < 32) {
        int w = warpsums[threadIdx.x]; int y = w;
        #pragma unroll
        for (int d = 1; d < 32; d <<= 1) { int t = __shfl_up_sync(~0u, y, d); if (threadIdx.x >= d) y += t; }
        warpsums[threadIdx.x] = y - w;
    }
    __syncthreads();
    x += warpsums[warp];
    if (i < NN) g_incl[i] = x;
    if (threadIdx.x == 1023) g_bsum[blockIdx.x] = x;
}
__global__ void k_scan_tot(int nb) {
    __shared__ int ws[4];
    int t = threadIdx.x, lane = t & 31, warp = t >> 5;
    int v = (t < nb) ? g_bsum[t] : 0;
    int x = v;
    #pragma unroll
    for (int d = 1; d < 32; d <<= 1) { int tt = __shfl_up_sync(~0u, x, d); if (lane >= d) x += tt; }
    if (lane == 31) ws[warp] = x;
    __syncthreads();
    if (t == 0) { int a = 0; for (int j = 0; j < 4; j++) { int tmp = ws[j]; ws[j] = a; a += tmp; } }
    __syncthreads();
    x += ws[warp];
    if (t < nb) g_boff[t] = x - v;
}
__global__ void k_finalize() {
    int i = blockIdx.x * blockDim.x + threadIdx.x;
    if (i < NN) {
        int d = g_deg[i];
        int rp = g_incl[i] + g_boff[i >> 10] - d;
        g_rowptr[i] = rp;
        g_cursor[i] = rp;
        g_invdeg[i] = 1.0f / (float)max(d, 1);
    }
    if (i == 0) g_rowptr[NN] = EE;
}
__global__ void k_fill(const int* __restrict__ src, const int* __restrict__ dst) {
    int e = blockIdx.x * blockDim.x + threadIdx.x;
    if (e < EE) { int p = atomicAdd(&g_cursor[dst[e]], 1); g_col[p] = src[e]; }
}

// ================= HMMA helpers (portable sm_80+ PTX) =================
__device__ __forceinline__ uint32_t smem_u32(const void* p) {
    uint32_t a;
    asm("{ .reg .u64 t; cvta.to.shared.u64 t, %1; cvt.u32.u64 %0, t; }" : "=r"(a) : "l"(p));
    return a;
}
__device__ __forceinline__ void ldm_x4(uint32_t* r, uint32_t addr) {
    asm volatile("ldmatrix.sync.aligned.m8n8.x4.shared.b16 {%0,%1,%2,%3}, [%4];"
        : "=r"(r[0]), "=r"(r[1]), "=r"(r[2]), "=r"(r[3]) : "r"(addr));
}
__device__ __forceinline__ void mma16816(float* d, const uint32_t* a, const uint32_t* b) {
    asm volatile("mma.sync.aligned.m16n8k16.row.col.f32.bf16.bf16.f32 "
        "{%0,%1,%2,%3}, {%4,%5,%6,%7}, {%8,%9}, {%0,%1,%2,%3};"
        : "+f"(d[0]), "+f"(d[1]), "+f"(d[2]), "+f"(d[3])
        : "r"(a[0]), "r"(a[1]), "r"(a[2]), "r"(a[3]), "r"(b[0]), "r"(b[1]));
}
// fp32 pair -> hi bf16x2 (ret) + lo bf16x2 (out param)
__device__ __forceinline__ uint32_t bfsplit2(float a, float b, uint32_t& lo) {
    __nv_bfloat16 h0 = __float2bfloat16_rn(a), h1 = __float2bfloat16_rn(b);
    float r0 = a - __bfloat162float(h0), r1 = b - __bfloat162float(h1);
    __nv_bfloat16 l0 = __float2bfloat16_rn(r0), l1 = __float2bfloat16_rn(r1);
    lo = (uint32_t)__bfloat16_as_ushort(l0) | ((uint32_t)__bfloat16_as_ushort(l1) << 16);
    return (uint32_t)__bfloat16_as_ushort(h0) | ((uint32_t)__bfloat16_as_ushort(h1) << 16);
}
// swizzled smem address: row stride 256B (128 bf16), 16B chunks XORed by row&7
__device__ __forceinline__ uint32_t swaddr(uint32_t base, int row, int chunk) {
    return base + (uint32_t)(row * 256) + (uint32_t)(((chunk ^ (row & 7)) << 4));
}

// ================= bf16 split-precision GEMM via mma.sync =================
// out[node][cg] = sum_k A[node][k] * W[cg][k],  W = [Wl ; Wr] stacked (NOUT rows).
// CTA: 512 thr, 16 warps (4m x 4n), tile 128 nodes x 128 cols, persistent over m-tiles.
// Register-prefetch pipeline: next tile's A float4s are LDG'd into registers
// during the current tile's MMA compute; only cvt+STS sits between the syncs.
// Cols [0,NH) -> uout (fp16), [NH,NOUT) -> vout (fp32); row stride NH each.
template <int NOUT>
__global__ void __launch_bounds__(512, 1)
k_mma_gemm(const float* __restrict__ Ain,
           const float* __restrict__ Wl, const float* __restrict__ Wr,
           __half* __restrict__ uout, float* __restrict__ vout)
{
    constexpr int NH = NOUT / 2;
    constexpr int NTILES = (NN + 127) / 128;
    constexpr uint32_t OFF_WH = 0, OFF_WL = 32768, OFF_AH = 65536, OFF_AL = 98304;

    extern __shared__ char sm[];
    uint32_t sb = smem_u32(sm);

    int tid = threadIdx.x;
    int wid = tid >> 5;
    int lane = tid & 31;
    int wm = wid & 3, wn = wid >> 2;
    int by = blockIdx.y;

    // ---- stage weights once (128 rows x 128 k, hi/lo) ----
    for (int idx = tid; idx < 128 * 32; idx += 512) {
        int r = idx >> 5, q = idx & 31;
        int gcol = by * 128 + r;
        const float* ws = (gcol < NH) ? (Wl + (size_t)gcol * HID + q * 4)
                                      : (Wr + (size_t)(gcol - NH) * HID + q * 4);
        float4 w = *(const float4*)ws;
        uint32_t l01, l23;
        uint32_t h01 = bfsplit2(w.x, w.y, l01);
        uint32_t h23 = bfsplit2(w.z, w.w, l23);
        uint32_t a = swaddr(sb, r, q >> 1) + (q & 1) * 8;
        *(uint2*)(sm + (a - sb) + OFF_WH) = make_uint2(h01, h23);
        *(uint2*)(sm + (a - sb) + OFF_WL) = make_uint2(l01, l23);
    }

    int lane15 = lane & 15, lhalf = lane >> 4;
    int t4 = lane & 3, g8 = lane >> 2;
    int mrow = wm * 32 + lane15;
    int nrow = wn * 32 + lane15;

    // register prefetch buffer: 8 float4 = this thread's share of a 128x128 tile
    float4 pf[8];
    auto do_prefetch = [&](int tile) {
        int nodebase = tile * 128;
        #pragma unroll
        for (int i = 0; i < 8; i++) {
            int idx = tid + i * 512;
            int r = idx >> 5, q = idx & 31;
            int node = nodebase + r;
            pf[i] = (node < NN) ? *(const float4*)(Ain + (size_t)node * HID + q * 4)
                                : make_float4(0.f, 0.f, 0.f, 0.f);
        }
    };

    int t0 = blockIdx.x;
    if (t0 < NTILES) do_prefetch(t0);

    for (int tile = t0; tile < NTILES; tile += gridDim.x) {
        int nodebase = tile * 128;
        __syncthreads();   // previous tile's compute done reading A smem

        // ---- split prefetched registers into smem hi/lo ----
        #pragma unroll
        for (int i = 0; i < 8; i++) {
            int idx = tid + i * 512;
            int r = idx >> 5, q = idx & 31;
            uint32_t l01, l23;
            uint32_t h01 = bfsplit2(pf[i].x, pf[i].y, l01);
            uint32_t h23 = bfsplit2(pf[i].z, pf[i].w, l23);
            uint32_t a = swaddr(sb, r, q >> 1) + (q & 1) * 8;
            *(uint2*)(sm + (a - sb) + OFF_AH) = make_uint2(h01, h23);
            *(uint2*)(sm + (a - sb) + OFF_AL) = make_uint2(l01, l23);
        }
        __syncthreads();

        // ---- issue next tile's LDGs; they retire under the MMAs below ----
        int nxt = tile + gridDim.x;
        if (nxt < NTILES) do_prefetch(nxt);

        // ---- compute: 8 k-steps, 3-way split, fp32 acc ----
        float acc[2][4][4];
        #pragma unroll
        for (int i = 0; i < 2; i++)
            #pragma unroll
            for (int j = 0; j < 4; j++)
                #pragma unroll
                for (int e = 0; e < 4; e++) acc[i][j][e] = 0.f;

        #pragma unroll
        for (int ks = 0; ks < 8; ks++) {
            int ch = ks * 2 + lhalf;
            uint32_t Ah[2][4], Al[2][4], Bh[4][2], Bl[4][2], tb[4];
            ldm_x4(Ah[0], swaddr(sb + OFF_AH, mrow,      ch));
            ldm_x4(Ah[1], swaddr(sb + OFF_AH, mrow + 16, ch));
            ldm_x4(Al[0], swaddr(sb + OFF_AL, mrow,      ch));
            ldm_x4(Al[1], swaddr(sb + OFF_AL, mrow + 16, ch));
            ldm_x4(tb, swaddr(sb + OFF_WH, nrow, ch));
            Bh[0][0] = tb[0]; Bh[0][1] = tb[2]; Bh[1][0] = tb[1]; Bh[1][1] = tb[3];
            ldm_x4(tb, swaddr(sb + OFF_WH, nrow + 16, ch));
            Bh[2][0] = tb[0]; Bh[2][1] = tb[2]; Bh[3][0] = tb[1]; Bh[3][1] = tb[3];
            ldm_x4(tb, swaddr(sb + OFF_WL, nrow, ch));
            Bl[0][0] = tb[0]; Bl[0][1] = tb[2]; Bl[1][0] = tb[1]; Bl[1][1] = tb[3];
            ldm_x4(tb, swaddr(sb + OFF_WL, nrow + 16, ch));
            Bl[2][0] = tb[0]; Bl[2][1] = tb[2]; Bl[3][0] = tb[1]; Bl[3][1] = tb[3];

            #pragma unroll
            for (int mi = 0; mi < 2; mi++)
                #pragma unroll
                for (int nf = 0; nf < 4; nf++) {
                    mma16816(acc[mi][nf], Ah[mi], Bh[nf]);
                    mma16816(acc[mi][nf], Al[mi], Bh[nf]);
                    mma16816(acc[mi][nf], Ah[mi], Bl[nf]);
                }
        }

        // ---- epilogue: u -> fp16 half2 stores, v -> fp32 float2 stores ----
        #pragma unroll
        for (int mi = 0; mi < 2; mi++) {
            int row0 = nodebase + wm * 32 + mi * 16 + g8;
            #pragma unroll
            for (int nf = 0; nf < 4; nf++) {
                int cg = by * 128 + wn * 32 + nf * 8 + 2 * t4;
                if (cg < NH) {
                    __half* dp = uout + cg;
                    if (row0 < NN)
                        *(half2*)(dp + (size_t)row0 * NH) =
                            __floats2half2_rn(acc[mi][nf][0], acc[mi][nf][1]);
                    if (row0 + 8 < NN)
                        *(half2*)(dp + (size_t)(row0 + 8) * NH) =
                            __floats2half2_rn(acc[mi][nf][2], acc[mi][nf][3]);
                } else {
                    float* dp = vout + (cg - NH);
                    if (row0 < NN)
                        *(float2*)(dp + (size_t)row0 * NH) =
                            make_float2(acc[mi][nf][0], acc[mi][nf][1]);
                    if (row0 + 8 < NN)
                        *(float2*)(dp + (size_t)(row0 + 8) * NH) =
                            make_float2(acc[mi][nf][2], acc[mi][nf][3]);
                }
            }
        }
    }
}

// ---------------- fused mean-aggregate + bias + BN + ReLU (layers 1,2) ----------------
// u rows are fp16: 128 halves = 256B; lane reads uint2 (4 halves) per neighbor.
__global__ void k_agg_bn(const __half* __restrict__ u, const float* __restrict__ v,
                         const float* __restrict__ bias, const float* __restrict__ gam,
                         const float* __restrict__ bet, const float* __restrict__ rmean,
                         const float* __restrict__ rvar, float* __restrict__ hout)
{
    int gw = (blockIdx.x * blockDim.x + threadIdx.x) >> 5;
    int lane = threadIdx.x & 31;
    if (gw >= NN) return;
    int s0 = g_rowptr[gw], s1 = g_rowptr[gw + 1];
    const uint2* ub = (const uint2*)u;   // row stride = 32 uint2
    float4 acc = make_float4(0.f, 0.f, 0.f, 0.f);
    for (int b = s0; b < s1; b += 32) {
        int cnt = s1 - b; if (cnt > 32) cnt = 32;
        int idxv = (lane < cnt) ? g_col[b + lane] : 0;
        for (int j = 0; j < cnt; j++) {
            int s = __shfl_sync(~0u, idxv, j);
            uint2 t = ub[(size_t)s * 32 + lane];
            float2 f0 = __half22float2(*(const half2*)&t.x);
            float2 f1 = __half22float2(*(const half2*)&t.y);
            acc.x += f0.x; acc.y += f0.y; acc.z += f1.x; acc.w += f1.y;
        }
    }
    float iv = g_invdeg[gw];
    int cb = lane * 4;
    float4 vv = *(const float4*)(v + (size_t)gw * HID + cb);
    float4 bb = *(const float4*)(bias + cb);
    float4 gg = *(const float4*)(gam + cb);
    float4 be = *(const float4*)(bet + cb);
    float4 rm = *(const float4*)(rmean + cb);
    float4 rv = *(const float4*)(rvar + cb);
    float4 o;
    o.x = fmaxf((acc.x * iv + bb.x + vv.x - rm.x) * (gg.x * rsqrtf(rv.x + BNEPS)) + be.x, 0.f);
    o.y = fmaxf((acc.y * iv + bb.y + vv.y - rm.y) * (gg.y * rsqrtf(rv.y + BNEPS)) + be.y, 0.f);
    o.z = fmaxf((acc.z * iv + bb.z + vv.z - rm.z) * (gg.z * rsqrtf(rv.z + BNEPS)) + be.z, 0.f);
    o.w = fmaxf((acc.w * iv + bb.w + vv.w - rm.w) * (gg.w * rsqrtf(rv.w + BNEPS)) + be.w, 0.f);
    *(float4*)(hout + (size_t)gw * HID + cb) = o;
}

// ---------------- layer 3: mean-aggregate(p fp16) + b3 + r, log_softmax ----------------
__global__ void k_agg_lsm(const __half* __restrict__ p, const float* __restrict__ r,
                          const float* __restrict__ b3, float* __restrict__ out)
{
    int gw = (blockIdx.x * blockDim.x + threadIdx.x) >> 5;
    int lane = threadIdx.x & 31;
    if (gw >= NN) return;
    int s0 = g_rowptr[gw], s1 = g_rowptr[gw + 1];
    const uint32_t* pb = (const uint32_t*)p;  // row stride = 32 uint32 (64 halves)
    float ax = 0.f, ay = 0.f;
    for (int b = s0; b < s1; b += 32) {
        int cnt = s1 - b; if (cnt > 32) cnt = 32;
        int idxv = (lane < cnt) ? g_col[b + lane] : 0;
        for (int j = 0; j < cnt; j++) {
            int s = __shfl_sync(~0u, idxv, j);
            uint32_t t = pb[(size_t)s * 32 + lane];
            float2 f = __half22float2(*(const half2*)&t);
            ax += f.x; ay += f.y;
        }
    }
    float iv = g_invdeg[gw];
    float2 rr = *(const float2*)(r + (size_t)gw * OUTC + lane * 2);
    float2 bb = *(const float2*)(b3 + lane * 2);
    float l0 = ax * iv + bb.x + rr.x;
    float l1 = ay * iv + bb.y + rr.y;
    float m = fmaxf(l0, l1);
    #pragma unroll
    for (int o = 16; o; o >>= 1) m = fmaxf(m, __shfl_xor_sync(~0u, m, o));
    float s = expf(l0 - m) + expf(l1 - m);
    #pragma unroll
    for (int o = 16; o; o >>= 1) s += __shfl_xor_sync(~0u, s, o);
    float lse = m + logf(s);
    float2 o2; o2.x = l0 - lse; o2.y = l1 - lse;
    *(float2*)(out + (size_t)gw * OUTC + lane * 2) = o2;
}

// ---------------- launch ----------------
extern "C" void kernel_launch(void* const* d_in, const int* in_sizes, int n_in,
                              void* d_out, int out_size)
{
    const float* x   = (const float*)d_in[0];
    const int*   src = (const int*)d_in[1];
    const int*   dst = (const int*)d_in[2];
    const float* W1l = (const float*)d_in[3];
    const float* W1r = (const float*)d_in[4];
    const float* b1  = (const float*)d_in[5];
    const float* g1  = (const float*)d_in[6];
    const float* be1 = (const float*)d_in[7];
    const float* rm1 = (const float*)d_in[8];
    const float* rv1 = (const float*)d_in[9];
    const float* W2l = (const float*)d_in[10];
    const float* W2r = (const float*)d_in[11];
    const float* b2  = (const float*)d_in[12];
    const float* g2  = (const float*)d_in[13];
    const float* be2 = (const float*)d_in[14];
    const float* rm2 = (const float*)d_in[15];
    const float* rv2 = (const float*)d_in[16];
    const float* W3l = (const float*)d_in[17];
    const float* W3r = (const float*)d_in[18];
    const float* b3  = (const float*)d_in[19];
    float* out = (float*)d_out;

    __half* u; float *v, *h;
    cudaGetSymbolAddress((void**)&u, g_u);
    cudaGetSymbolAddress((void**)&v, g_v);
    cudaGetSymbolAddress((void**)&h, g_h);

    // one-time host-side objects (created on first/correctness call, reused; never during capture)
    static cudaStream_t s2 = nullptr;
    static cudaEvent_t ev_fork = nullptr, ev_join = nullptr;
    if (!s2) {
        cudaStreamCreateWithFlags(&s2, cudaStreamNonBlocking);
        cudaEventCreateWithFlags(&ev_fork, cudaEventDisableTiming);
        cudaEventCreateWithFlags(&ev_join, cudaEventDisableTiming);
    }

    const int NB = (NN + 1023) >> 10;
    const int SMEM = 131072;
    cudaFuncSetAttribute(k_mma_gemm<256>, cudaFuncAttributeMaxDynamicSharedMemorySize, SMEM);
    cudaFuncSetAttribute(k_mma_gemm<128>, cudaFuncAttributeMaxDynamicSharedMemorySize, SMEM);

    const int AGG_BLOCKS = (NN * 32 + 255) / 256;

    // ---- fork: CSR build on s2, layer-1 GEMM on main stream, join before agg ----
    cudaEventRecord(ev_fork, 0);
    cudaStreamWaitEvent(s2, ev_fork, 0);
    k_zero_deg<<<(NN + 255) / 256, 256, 0, s2>>>();
    k_count<<<(EE + 255) / 256, 256, 0, s2>>>(dst);
    k_scan_block<<<NB, 1024, 0, s2>>>();
    k_scan_tot<<<1, 128, 0, s2>>>(NB);
    k_finalize<<<(NN + 255) / 256, 256, 0, s2>>>();
    k_fill<<<(EE + 255) / 256, 256, 0, s2>>>(src, dst);
    cudaEventRecord(ev_join, s2);

    // Layer 1 GEMM overlaps CSR build
    k_mma_gemm<256><<<dim3(74, 2), 512, SMEM>>>(x, W1l, W1r, u, v);
    cudaStreamWaitEvent(0, ev_join, 0);
    k_agg_bn<<<AGG_BLOCKS, 256>>>(u, v, b1, g1, be1, rm1, rv1, h);
    // Layer 2
    k_mma_gemm<256><<<dim3(74, 2), 512, SMEM>>>(h, W2l, W2r, u, v);
    k_agg_bn<<<AGG_BLOCKS, 256>>>(u, v, b2, g2, be2, rm2, rv2, h);
    // Layer 3: project h -> [p|r] (64 each), aggregate p, add b3+r, log_softmax
    k_mma_gemm<128><<<dim3(148, 1), 512, SMEM>>>(h, W3l, W3r, u, v);
    k_agg_lsm<<<AGG_BLOCKS, 256>>>(u, v, b3, out);
}

// round 13
// speedup vs baseline: 1.5862x; 1.0039x over previous
#include <cuda_runtime.h>
#include <cuda_bf16.h>
#include <cuda_fp16.h>
#include <cstdint>
#include <math.h>

#define NN   100000
#define EE   1600000
#define HID  128
#define OUTC 64
#define BNEPS 1e-5f

// ---------------- scratch (static device globals; no allocation) ----------------
__device__ int   g_deg[NN];
__device__ int   g_incl[NN];
__device__ int   g_bsum[128];
__device__ int   g_boff[128];
__device__ int   g_rowptr[NN + 1];
__device__ int   g_cursor[NN];
__device__ int   g_col[EE];
__device__ float g_invdeg[NN];
__device__ __half g_u[(size_t)NN * HID];  // projected "left" features (to aggregate), fp16
__device__ float g_v[(size_t)NN * HID];   // projected "right" features (self), fp32
__device__ float g_h[(size_t)NN * HID];   // layer activations

// ---------------- CSR build ----------------
__global__ void k_zero_deg() {
    int i = blockIdx.x * blockDim.x + threadIdx.x;
    if (i < NN) g_deg[i] = 0;
}
__global__ void k_count(const int* __restrict__ dst) {
    int e = blockIdx.x * blockDim.x + threadIdx.x;
    if (e < EE) atomicAdd(&g_deg[dst[e]], 1);
}
__global__ void k_scan_block() {
    __shared__ int warpsums[32];
    int i = blockIdx.x * 1024 + threadIdx.x;
    int lane = threadIdx.x & 31, warp = threadIdx.x >> 5;
    int v = (i < NN) ? g_deg[i] : 0;
    int x = v;
    #pragma unroll
    for (int d = 1; d < 32; d <<= 1) { int t = __shfl_up_sync(~0u, x, d); if (lane >= d) x += t; }
    if (lane == 31) warpsums[warp] = x;
    __syncthreads();
    if (threadIdx.x < 32) {
        int w = warpsums[threadIdx.x]; int y = w;
        #pragma unroll
        for (int d = 1; d < 32; d <<= 1) { int t = __shfl_up_sync(~0u, y, d); if (threadIdx.x >= d) y += t; }
        warpsums[threadIdx.x] = y - w;
    }
    __syncthreads();
    x += warpsums[warp];
    if (i < NN) g_incl[i] = x;
    if (threadIdx.x == 1023) g_bsum[blockIdx.x] = x;
}
__global__ void k_scan_tot(int nb) {
    __shared__ int ws[4];
    int t = threadIdx.x, lane = t & 31, warp = t >> 5;
    int v = (t < nb) ? g_bsum[t] : 0;
    int x = v;
    #pragma unroll
    for (int d = 1; d < 32; d <<= 1) { int tt = __shfl_up_sync(~0u, x, d); if (lane >= d) x += tt; }
    if (lane == 31) ws[warp] = x;
    __syncthreads();
    if (t == 0) { int a = 0; for (int j = 0; j < 4; j++) { int tmp = ws[j]; ws[j] = a; a += tmp; } }
    __syncthreads();
    x += ws[warp];
    if (t < nb) g_boff[t] = x - v;
}
__global__ void k_finalize() {
    int i = blockIdx.x * blockDim.x + threadIdx.x;
    if (i < NN) {
        int d = g_deg[i];
        int rp = g_incl[i] + g_boff[i >> 10] - d;
        g_rowptr[i] = rp;
        g_cursor[i] = rp;
        g_invdeg[i] = 1.0f / (float)max(d, 1);
    }
    if (i == 0) g_rowptr[NN] = EE;
}
__global__ void k_fill(const int* __restrict__ src, const int* __restrict__ dst) {
    int e = blockIdx.x * blockDim.x + threadIdx.x;
    if (e < EE) { int p = atomicAdd(&g_cursor[dst[e]], 1); g_col[p] = src[e]; }
}

// ================= HMMA helpers (portable sm_80+ PTX) =================
__device__ __forceinline__ uint32_t smem_u32(const void* p) {
    uint32_t a;
    asm("{ .reg .u64 t; cvta.to.shared.u64 t, %1; cvt.u32.u64 %0, t; }" : "=r"(a) : "l"(p));
    return a;
}
__device__ __forceinline__ void ldm_x4(uint32_t* r, uint32_t addr) {
    asm volatile("ldmatrix.sync.aligned.m8n8.x4.shared.b16 {%0,%1,%2,%3}, [%4];"
        : "=r"(r[0]), "=r"(r[1]), "=r"(r[2]), "=r"(r[3]) : "r"(addr));
}
__device__ __forceinline__ void mma16816(float* d, const uint32_t* a, const uint32_t* b) {
    asm volatile("mma.sync.aligned.m16n8k16.row.col.f32.bf16.bf16.f32 "
        "{%0,%1,%2,%3}, {%4,%5,%6,%7}, {%8,%9}, {%0,%1,%2,%3};"
        : "+f"(d[0]), "+f"(d[1]), "+f"(d[2]), "+f"(d[3])
        : "r"(a[0]), "r"(a[1]), "r"(a[2]), "r"(a[3]), "r"(b[0]), "r"(b[1]));
}
// fp32 pair -> hi bf16x2 (ret) + lo bf16x2 (out param)
__device__ __forceinline__ uint32_t bfsplit2(float a, float b, uint32_t& lo) {
    __nv_bfloat16 h0 = __float2bfloat16_rn(a), h1 = __float2bfloat16_rn(b);
    float r0 = a - __bfloat162float(h0), r1 = b - __bfloat162float(h1);
    __nv_bfloat16 l0 = __float2bfloat16_rn(r0), l1 = __float2bfloat16_rn(r1);
    lo = (uint32_t)__bfloat16_as_ushort(l0) | ((uint32_t)__bfloat16_as_ushort(l1) << 16);
    return (uint32_t)__bfloat16_as_ushort(h0) | ((uint32_t)__bfloat16_as_ushort(h1) << 16);
}
// swizzled smem address: row stride 256B (128 bf16), 16B chunks XORed by row&7
__device__ __forceinline__ uint32_t swaddr(uint32_t base, int row, int chunk) {
    return base + (uint32_t)(row * 256) + (uint32_t)(((chunk ^ (row & 7)) << 4));
}

// ================= bf16 split-precision GEMM via mma.sync =================
// out[node][cg] = sum_k A[node][k] * W[cg][k],  W = [Wl ; Wr] stacked (NOUT rows).
// CTA: 512 thr, 16 warps (4m x 4n), tile 128 nodes x 128 cols, persistent over m-tiles.
// Register-prefetch pipeline: next tile's A float4s are LDG'd into registers
// during the current tile's MMA compute; only cvt+STS sits between the syncs.
// Cols [0,NH) -> uout (fp16), [NH,NOUT) -> vout (fp32); row stride NH each.
template <int NOUT>
__global__ void __launch_bounds__(512, 1)
k_mma_gemm(const float* __restrict__ Ain,
           const float* __restrict__ Wl, const float* __restrict__ Wr,
           __half* __restrict__ uout, float* __restrict__ vout)
{
    constexpr int NH = NOUT / 2;
    constexpr int NTILES = (NN + 127) / 128;
    constexpr uint32_t OFF_WH = 0, OFF_WL = 32768, OFF_AH = 65536, OFF_AL = 98304;

    extern __shared__ char sm[];
    uint32_t sb = smem_u32(sm);

    int tid = threadIdx.x;
    int wid = tid >> 5;
    int lane = tid & 31;
    int wm = wid & 3, wn = wid >> 2;
    int by = blockIdx.y;

    // ---- stage weights once (128 rows x 128 k, hi/lo) ----
    for (int idx = tid; idx < 128 * 32; idx += 512) {
        int r = idx >> 5, q = idx & 31;
        int gcol = by * 128 + r;
        const float* ws = (gcol < NH) ? (Wl + (size_t)gcol * HID + q * 4)
                                      : (Wr + (size_t)(gcol - NH) * HID + q * 4);
        float4 w = *(const float4*)ws;
        uint32_t l01, l23;
        uint32_t h01 = bfsplit2(w.x, w.y, l01);
        uint32_t h23 = bfsplit2(w.z, w.w, l23);
        uint32_t a = swaddr(sb, r, q >> 1) + (q & 1) * 8;
        *(uint2*)(sm + (a - sb) + OFF_WH) = make_uint2(h01, h23);
        *(uint2*)(sm + (a - sb) + OFF_WL) = make_uint2(l01, l23);
    }

    int lane15 = lane & 15, lhalf = lane >> 4;
    int t4 = lane & 3, g8 = lane >> 2;
    int mrow = wm * 32 + lane15;
    int nrow = wn * 32 + lane15;

    // register prefetch buffer: 8 float4 = this thread's share of a 128x128 tile
    float4 pf[8];
    auto do_prefetch = [&](int tile) {
        int nodebase = tile * 128;
        #pragma unroll
        for (int i = 0; i < 8; i++) {
            int idx = tid + i * 512;
            int r = idx >> 5, q = idx & 31;
            int node = nodebase + r;
            pf[i] = (node < NN) ? *(const float4*)(Ain + (size_t)node * HID + q * 4)
                                : make_float4(0.f, 0.f, 0.f, 0.f);
        }
    };

    int t0 = blockIdx.x;
    if (t0 < NTILES) do_prefetch(t0);

    for (int tile = t0; tile < NTILES; tile += gridDim.x) {
        int nodebase = tile * 128;
        __syncthreads();   // previous tile's compute done reading A smem

        // ---- split prefetched registers into smem hi/lo ----
        #pragma unroll
        for (int i = 0; i < 8; i++) {
            int idx = tid + i * 512;
            int r = idx >> 5, q = idx & 31;
            uint32_t l01, l23;
            uint32_t h01 = bfsplit2(pf[i].x, pf[i].y, l01);
            uint32_t h23 = bfsplit2(pf[i].z, pf[i].w, l23);
            uint32_t a = swaddr(sb, r, q >> 1) + (q & 1) * 8;
            *(uint2*)(sm + (a - sb) + OFF_AH) = make_uint2(h01, h23);
            *(uint2*)(sm + (a - sb) + OFF_AL) = make_uint2(l01, l23);
        }
        __syncthreads();

        // ---- issue next tile's LDGs; they retire under the MMAs below ----
        int nxt = tile + gridDim.x;
        if (nxt < NTILES) do_prefetch(nxt);

        // ---- compute: 8 k-steps, 3-way split, fp32 acc ----
        float acc[2][4][4];
        #pragma unroll
        for (int i = 0; i < 2; i++)
            #pragma unroll
            for (int j = 0; j < 4; j++)
                #pragma unroll
                for (int e = 0; e < 4; e++) acc[i][j][e] = 0.f;

        #pragma unroll
        for (int ks = 0; ks < 8; ks++) {
            int ch = ks * 2 + lhalf;
            uint32_t Ah[2][4], Al[2][4], Bh[4][2], Bl[4][2], tb[4];
            ldm_x4(Ah[0], swaddr(sb + OFF_AH, mrow,      ch));
            ldm_x4(Ah[1], swaddr(sb + OFF_AH, mrow + 16, ch));
            ldm_x4(Al[0], swaddr(sb + OFF_AL, mrow,      ch));
            ldm_x4(Al[1], swaddr(sb + OFF_AL, mrow + 16, ch));
            ldm_x4(tb, swaddr(sb + OFF_WH, nrow, ch));
            Bh[0][0] = tb[0]; Bh[0][1] = tb[2]; Bh[1][0] = tb[1]; Bh[1][1] = tb[3];
            ldm_x4(tb, swaddr(sb + OFF_WH, nrow + 16, ch));
            Bh[2][0] = tb[0]; Bh[2][1] = tb[2]; Bh[3][0] = tb[1]; Bh[3][1] = tb[3];
            ldm_x4(tb, swaddr(sb + OFF_WL, nrow, ch));
            Bl[0][0] = tb[0]; Bl[0][1] = tb[2]; Bl[1][0] = tb[1]; Bl[1][1] = tb[3];
            ldm_x4(tb, swaddr(sb + OFF_WL, nrow + 16, ch));
            Bl[2][0] = tb[0]; Bl[2][1] = tb[2]; Bl[3][0] = tb[1]; Bl[3][1] = tb[3];

            #pragma unroll
            for (int mi = 0; mi < 2; mi++)
                #pragma unroll
                for (int nf = 0; nf < 4; nf++) {
                    mma16816(acc[mi][nf], Ah[mi], Bh[nf]);
                    mma16816(acc[mi][nf], Al[mi], Bh[nf]);
                    mma16816(acc[mi][nf], Ah[mi], Bl[nf]);
                }
        }

        // ---- epilogue: u -> fp16 half2 stores, v -> fp32 float2 stores ----
        #pragma unroll
        for (int mi = 0; mi < 2; mi++) {
            int row0 = nodebase + wm * 32 + mi * 16 + g8;
            #pragma unroll
            for (int nf = 0; nf < 4; nf++) {
                int cg = by * 128 + wn * 32 + nf * 8 + 2 * t4;
                if (cg < NH) {
                    __half* dp = uout + cg;
                    if (row0 < NN)
                        *(half2*)(dp + (size_t)row0 * NH) =
                            __floats2half2_rn(acc[mi][nf][0], acc[mi][nf][1]);
                    if (row0 + 8 < NN)
                        *(half2*)(dp + (size_t)(row0 + 8) * NH) =
                            __floats2half2_rn(acc[mi][nf][2], acc[mi][nf][3]);
                } else {
                    float* dp = vout + (cg - NH);
                    if (row0 < NN)
                        *(float2*)(dp + (size_t)row0 * NH) =
                            make_float2(acc[mi][nf][0], acc[mi][nf][1]);
                    if (row0 + 8 < NN)
                        *(float2*)(dp + (size_t)(row0 + 8) * NH) =
                            make_float2(acc[mi][nf][2], acc[mi][nf][3]);
                }
            }
        }
    }
}

// ---------------- fused mean-aggregate + bias + BN + ReLU (layers 1,2) ----------------
// 4-deep batched gather: 4 independent LDG.64 in flight per warp (MLP=4).
__global__ void k_agg_bn(const __half* __restrict__ u, const float* __restrict__ v,
                         const float* __restrict__ bias, const float* __restrict__ gam,
                         const float* __restrict__ bet, const float* __restrict__ rmean,
                         const float* __restrict__ rvar, float* __restrict__ hout)
{
    int gw = (blockIdx.x * blockDim.x + threadIdx.x) >> 5;
    int lane = threadIdx.x & 31;
    if (gw >= NN) return;
    int s0 = g_rowptr[gw], s1 = g_rowptr[gw + 1];
    const uint2* ub = (const uint2*)u;   // row stride = 32 uint2
    float4 acc = make_float4(0.f, 0.f, 0.f, 0.f);
    for (int b = s0; b < s1; b += 32) {
        int cnt = s1 - b; if (cnt > 32) cnt = 32;
        int idxv = (lane < cnt) ? g_col[b + lane] : 0;
        for (int j = 0; j < cnt; j += 4) {
            uint2 t[4]; float p[4];
            #pragma unroll
            for (int q = 0; q < 4; q++) {
                int jq = j + q;
                int s = __shfl_sync(~0u, idxv, jq & 31);
                bool valid = jq < cnt;
                p[q] = valid ? 1.f : 0.f;
                t[q] = ub[(size_t)(valid ? s : 0) * 32 + lane];
            }
            #pragma unroll
            for (int q = 0; q < 4; q++) {
                float2 f0 = __half22float2(*(const half2*)&t[q].x);
                float2 f1 = __half22float2(*(const half2*)&t[q].y);
                acc.x = fmaf(p[q], f0.x, acc.x);
                acc.y = fmaf(p[q], f0.y, acc.y);
                acc.z = fmaf(p[q], f1.x, acc.z);
                acc.w = fmaf(p[q], f1.y, acc.w);
            }
        }
    }
    float iv = g_invdeg[gw];
    int cb = lane * 4;
    float4 vv = *(const float4*)(v + (size_t)gw * HID + cb);
    float4 bb = *(const float4*)(bias + cb);
    float4 gg = *(const float4*)(gam + cb);
    float4 be = *(const float4*)(bet + cb);
    float4 rm = *(const float4*)(rmean + cb);
    float4 rv = *(const float4*)(rvar + cb);
    float4 o;
    o.x = fmaxf((acc.x * iv + bb.x + vv.x - rm.x) * (gg.x * rsqrtf(rv.x + BNEPS)) + be.x, 0.f);
    o.y = fmaxf((acc.y * iv + bb.y + vv.y - rm.y) * (gg.y * rsqrtf(rv.y + BNEPS)) + be.y, 0.f);
    o.z = fmaxf((acc.z * iv + bb.z + vv.z - rm.z) * (gg.z * rsqrtf(rv.z + BNEPS)) + be.z, 0.f);
    o.w = fmaxf((acc.w * iv + bb.w + vv.w - rm.w) * (gg.w * rsqrtf(rv.w + BNEPS)) + be.w, 0.f);
    *(float4*)(hout + (size_t)gw * HID + cb) = o;
}

// ---------------- layer 3: mean-aggregate(p fp16) + b3 + r, log_softmax ----------------
__global__ void k_agg_lsm(const __half* __restrict__ p, const float* __restrict__ r,
                          const float* __restrict__ b3, float* __restrict__ out)
{
    int gw = (blockIdx.x * blockDim.x + threadIdx.x) >> 5;
    int lane = threadIdx.x & 31;
    if (gw >= NN) return;
    int s0 = g_rowptr[gw], s1 = g_rowptr[gw + 1];
    const uint32_t* pb = (const uint32_t*)p;  // row stride = 32 uint32 (64 halves)
    float ax = 0.f, ay = 0.f;
    for (int b = s0; b < s1; b += 32) {
        int cnt = s1 - b; if (cnt > 32) cnt = 32;
        int idxv = (lane < cnt) ? g_col[b + lane] : 0;
        for (int j = 0; j < cnt; j += 4) {
            uint32_t t[4]; float pw[4];
            #pragma unroll
            for (int q = 0; q < 4; q++) {
                int jq = j + q;
                int s = __shfl_sync(~0u, idxv, jq & 31);
                bool valid = jq < cnt;
                pw[q] = valid ? 1.f : 0.f;
                t[q] = pb[(size_t)(valid ? s : 0) * 32 + lane];
            }
            #pragma unroll
            for (int q = 0; q < 4; q++) {
                float2 f = __half22float2(*(const half2*)&t[q]);
                ax = fmaf(pw[q], f.x, ax);
                ay = fmaf(pw[q], f.y, ay);
            }
        }
    }
    float iv = g_invdeg[gw];
    float2 rr = *(const float2*)(r + (size_t)gw * OUTC + lane * 2);
    float2 bb = *(const float2*)(b3 + lane * 2);
    float l0 = ax * iv + bb.x + rr.x;
    float l1 = ay * iv + bb.y + rr.y;
    float m = fmaxf(l0, l1);
    #pragma unroll
    for (int o = 16; o; o >>= 1) m = fmaxf(m, __shfl_xor_sync(~0u, m, o));
    float s = expf(l0 - m) + expf(l1 - m);
    #pragma unroll
    for (int o = 16; o; o >>= 1) s += __shfl_xor_sync(~0u, s, o);
    float lse = m + logf(s);
    float2 o2; o2.x = l0 - lse; o2.y = l1 - lse;
    *(float2*)(out + (size_t)gw * OUTC + lane * 2) = o2;
}

// ---------------- launch ----------------
extern "C" void kernel_launch(void* const* d_in, const int* in_sizes, int n_in,
                              void* d_out, int out_size)
{
    const float* x   = (const float*)d_in[0];
    const int*   src = (const int*)d_in[1];
    const int*   dst = (const int*)d_in[2];
    const float* W1l = (const float*)d_in[3];
    const float* W1r = (const float*)d_in[4];
    const float* b1  = (const float*)d_in[5];
    const float* g1  = (const float*)d_in[6];
    const float* be1 = (const float*)d_in[7];
    const float* rm1 = (const float*)d_in[8];
    const float* rv1 = (const float*)d_in[9];
    const float* W2l = (const float*)d_in[10];
    const float* W2r = (const float*)d_in[11];
    const float* b2  = (const float*)d_in[12];
    const float* g2  = (const float*)d_in[13];
    const float* be2 = (const float*)d_in[14];
    const float* rm2 = (const float*)d_in[15];
    const float* rv2 = (const float*)d_in[16];
    const float* W3l = (const float*)d_in[17];
    const float* W3r = (const float*)d_in[18];
    const float* b3  = (const float*)d_in[19];
    float* out = (float*)d_out;

    __half* u; float *v, *h;
    cudaGetSymbolAddress((void**)&u, g_u);
    cudaGetSymbolAddress((void**)&v, g_v);
    cudaGetSymbolAddress((void**)&h, g_h);

    // one-time host-side objects (created on first/correctness call, reused; never during capture)
    static cudaStream_t s2 = nullptr;
    static cudaEvent_t ev_fork = nullptr, ev_join = nullptr;
    if (!s2) {
        cudaStreamCreateWithFlags(&s2, cudaStreamNonBlocking);
        cudaEventCreateWithFlags(&ev_fork, cudaEventDisableTiming);
        cudaEventCreateWithFlags(&ev_join, cudaEventDisableTiming);
    }

    const int NB = (NN + 1023) >> 10;
    const int SMEM = 131072;
    cudaFuncSetAttribute(k_mma_gemm<256>, cudaFuncAttributeMaxDynamicSharedMemorySize, SMEM);
    cudaFuncSetAttribute(k_mma_gemm<128>, cudaFuncAttributeMaxDynamicSharedMemorySize, SMEM);

    const int AGG_BLOCKS = (NN * 32 + 255) / 256;

    // ---- fork: CSR build on s2, layer-1 GEMM on main stream, join before agg ----
    cudaEventRecord(ev_fork, 0);
    cudaStreamWaitEvent(s2, ev_fork, 0);
    k_zero_deg<<<(NN + 255) / 256, 256, 0, s2>>>();
    k_count<<<(EE + 255) / 256, 256, 0, s2>>>(dst);
    k_scan_block<<<NB, 1024, 0, s2>>>();
    k_scan_tot<<<1, 128, 0, s2>>>(NB);
    k_finalize<<<(NN + 255) / 256, 256, 0, s2>>>();
    k_fill<<<(EE + 255) / 256, 256, 0, s2>>>(src, dst);
    cudaEventRecord(ev_join, s2);

    // Layer 1 GEMM overlaps CSR build
    k_mma_gemm<256><<<dim3(74, 2), 512, SMEM>>>(x, W1l, W1r, u, v);
    cudaStreamWaitEvent(0, ev_join, 0);
    k_agg_bn<<<AGG_BLOCKS, 256>>>(u, v, b1, g1, be1, rm1, rv1, h);
    // Layer 2
    k_mma_gemm<256><<<dim3(74, 2), 512, SMEM>>>(h, W2l, W2r, u, v);
    k_agg_bn<<<AGG_BLOCKS, 256>>>(u, v, b2, g2, be2, rm2, rv2, h);
    // Layer 3: project h -> [p|r] (64 each), aggregate p, add b3+r, log_softmax
    k_mma_gemm<128><<<dim3(148, 1), 512, SMEM>>>(h, W3l, W3r, u, v);
    k_agg_lsm<<<AGG_BLOCKS, 256>>>(u, v, b3, out);
}

// round 16
// speedup vs baseline: 1.6375x; 1.0323x over previous
#include <cuda_runtime.h>
#include <cuda_bf16.h>
#include <cuda_fp16.h>
#include <cstdint>
#include <math.h>

#define NN   100000
#define EE   1600000
#define HID  128
#define OUTC 64
#define BNEPS 1e-5f

// ---------------- scratch (static device globals; no allocation) ----------------
__device__ int   g_deg[NN];
__device__ int   g_incl[NN];
__device__ int   g_bsum[128];
__device__ int   g_boff[128];
__device__ int   g_rowptr[NN + 1];
__device__ int   g_cursor[NN];
__device__ int   g_col[EE];
__device__ float g_invdeg[NN];
__device__ __half g_u[(size_t)NN * HID];  // scaled left projection (to aggregate), fp16
__device__ float g_v[(size_t)NN * HID];   // right projection (+BN shift), fp16 L1/2, fp32 L3
__device__ float g_h[(size_t)NN * HID];   // layer activations, fp16

// ---------------- CSR build ----------------
__global__ void k_zero_deg() {
    int i = blockIdx.x * blockDim.x + threadIdx.x;
    if (i < NN) g_deg[i] = 0;
}
__global__ void k_count(const int* __restrict__ dst) {
    int e = blockIdx.x * blockDim.x + threadIdx.x;
    if (e < EE) atomicAdd(&g_deg[dst[e]], 1);
}
__global__ void k_scan_block() {
    __shared__ int warpsums[32];
    int i = blockIdx.x * 1024 + threadIdx.x;
    int lane = threadIdx.x & 31, warp = threadIdx.x >> 5;
    int v = (i < NN) ? g_deg[i] : 0;
    int x = v;
    #pragma unroll
    for (int d = 1; d < 32; d <<= 1) { int t = __shfl_up_sync(~0u, x, d); if (lane >= d) x += t; }
    if (lane == 31) warpsums[warp] = x;
    __syncthreads();
    if (threadIdx.x < 32) {
        int w = warpsums[threadIdx.x]; int y = w;
        #pragma unroll
        for (int d = 1; d < 32; d <<= 1) { int t = __shfl_up_sync(~0u, y, d); if (threadIdx.x >= d) y += t; }
        warpsums[threadIdx.x] = y - w;
    }
    __syncthreads();
    x += warpsums[warp];
    if (i < NN) g_incl[i] = x;
    if (threadIdx.x == 1023) g_bsum[blockIdx.x] = x;
}
__global__ void k_scan_tot(int nb) {
    __shared__ int ws[4];
    int t = threadIdx.x, lane = t & 31, warp = t >> 5;
    int v = (t < nb) ? g_bsum[t] : 0;
    int x = v;
    #pragma unroll
    for (int d = 1; d < 32; d <<= 1) { int tt = __shfl_up_sync(~0u, x, d); if (lane >= d) x += tt; }
    if (lane == 31) ws[warp] = x;
    __syncthreads();
    if (t == 0) { int a = 0; for (int j = 0; j < 4; j++) { int tmp = ws[j]; ws[j] = a; a += tmp; } }
    __syncthreads();
    x += ws[warp];
    if (t < nb) g_boff[t] = x - v;
}
__global__ void k_finalize() {
    int i = blockIdx.x * blockDim.x + threadIdx.x;
    if (i < NN) {
        int d = g_deg[i];
        int rp = g_incl[i] + g_boff[i >> 10] - d;
        g_rowptr[i] = rp;
        g_cursor[i] = rp;
        g_invdeg[i] = 1.0f / (float)max(d, 1);
    }
    if (i == 0) g_rowptr[NN] = EE;
}
__global__ void k_fill(const int* __restrict__ src, const int* __restrict__ dst) {
    int e = blockIdx.x * blockDim.x + threadIdx.x;
    if (e < EE) { int p = atomicAdd(&g_cursor[dst[e]], 1); g_col[p] = src[e]; }
}

// ================= HMMA helpers (portable sm_80+ PTX) =================
__device__ __forceinline__ uint32_t smem_u32(const void* p) {
    uint32_t a;
    asm("{ .reg .u64 t; cvta.to.shared.u64 t, %1; cvt.u32.u64 %0, t; }" : "=r"(a) : "l"(p));
    return a;
}
__device__ __forceinline__ void ldm_x4(uint32_t* r, uint32_t addr) {
    asm volatile("ldmatrix.sync.aligned.m8n8.x4.shared.b16 {%0,%1,%2,%3}, [%4];"
        : "=r"(r[0]), "=r"(r[1]), "=r"(r[2]), "=r"(r[3]) : "r"(addr));
}
__device__ __forceinline__ void mma16816(float* d, const uint32_t* a, const uint32_t* b) {
    asm volatile("mma.sync.aligned.m16n8k16.row.col.f32.bf16.bf16.f32 "
        "{%0,%1,%2,%3}, {%4,%5,%6,%7}, {%8,%9}, {%0,%1,%2,%3};"
        : "+f"(d[0]), "+f"(d[1]), "+f"(d[2]), "+f"(d[3])
        : "r"(a[0]), "r"(a[1]), "r"(a[2]), "r"(a[3]), "r"(b[0]), "r"(b[1]));
}
// fp32 pair -> hi bf16x2 (ret) + lo bf16x2 (out param)
__device__ __forceinline__ uint32_t bfsplit2(float a, float b, uint32_t& lo) {
    __nv_bfloat16 h0 = __float2bfloat16_rn(a), h1 = __float2bfloat16_rn(b);
    float r0 = a - __bfloat162float(h0), r1 = b - __bfloat162float(h1);
    __nv_bfloat16 l0 = __float2bfloat16_rn(r0), l1 = __float2bfloat16_rn(r1);
    lo = (uint32_t)__bfloat16_as_ushort(l0) | ((uint32_t)__bfloat16_as_ushort(l1) << 16);
    return (uint32_t)__bfloat16_as_ushort(h0) | ((uint32_t)__bfloat16_as_ushort(h1) << 16);
}
// swizzled smem address: row stride 256B (128 bf16), 16B chunks XORed by row&7
__device__ __forceinline__ uint32_t swaddr(uint32_t base, int row, int chunk) {
    return base + (uint32_t)(row * 256) + (uint32_t)(((chunk ^ (row & 7)) << 4));
}

// ================= bf16 split-precision GEMM via mma.sync =================
// EPI=0: BN folded — u' = acc*sc[c] (fp16), v' = acc*sc[c]+sh[c] (fp16).
// EPI=1: u = acc (fp16), v' = acc + bias[c] (fp32).
// AT = float (layer-1 input x) or __half (h from previous layer; exact bf16 hi/lo split).
template <int NOUT, int EPI, typename AT>
__global__ void __launch_bounds__(512, 1)
k_mma_gemm(const AT* __restrict__ Ain,
           const float* __restrict__ Wl, const float* __restrict__ Wr,
           const float* __restrict__ bias, const float* __restrict__ gam,
           const float* __restrict__ bet, const float* __restrict__ rmean,
           const float* __restrict__ rvar,
           __half* __restrict__ uout, void* __restrict__ vout_)
{
    constexpr int NH = NOUT / 2;
    constexpr int NTILES = (NN + 127) / 128;
    constexpr uint32_t OFF_WH = 0, OFF_WL = 32768, OFF_AH = 65536, OFF_AL = 98304;
    constexpr uint32_t OFF_SC = 131072, OFF_SH = 131584;

    extern __shared__ char sm[];
    uint32_t sb = smem_u32(sm);
    float* sSC = (float*)(sm + OFF_SC);
    float* sSH = (float*)(sm + OFF_SH);

    int tid = threadIdx.x;
    int wid = tid >> 5;
    int lane = tid & 31;
    int wm = wid & 3, wn = wid >> 2;
    int by = blockIdx.y;

    // ---- stage BN scale/shift (EPI=0) ----
    if constexpr (EPI == 0) {
        if (tid < 128) {
            float s = gam[tid] * rsqrtf(rvar[tid] + BNEPS);
            sSC[tid] = s;
            sSH[tid] = (bias[tid] - rmean[tid]) * s + bet[tid];
        }
    }

    // ---- stage weights once (128 rows x 128 k, hi/lo) ----
    for (int idx = tid; idx < 128 * 32; idx += 512) {
        int r = idx >> 5, q = idx & 31;
        int gcol = by * 128 + r;
        const float* ws = (gcol < NH) ? (Wl + (size_t)gcol * HID + q * 4)
                                      : (Wr + (size_t)(gcol - NH) * HID + q * 4);
        float4 w = *(const float4*)ws;
        uint32_t l01, l23;
        uint32_t h01 = bfsplit2(w.x, w.y, l01);
        uint32_t h23 = bfsplit2(w.z, w.w, l23);
        uint32_t a = swaddr(sb, r, q >> 1) + (q & 1) * 8;
        *(uint2*)(sm + (a - sb) + OFF_WH) = make_uint2(h01, h23);
        *(uint2*)(sm + (a - sb) + OFF_WL) = make_uint2(l01, l23);
    }

    int lane15 = lane & 15, lhalf = lane >> 4;
    int t4 = lane & 3, g8 = lane >> 2;
    int mrow = wm * 32 + lane15;
    int nrow = wn * 32 + lane15;

    // register prefetch buffer: 8 quads (4 elems each) per thread
    float4 pf[8];
    auto load4 = [&](int node, int q) -> float4 {
        if constexpr (sizeof(AT) == 4) {
            return *(const float4*)((const float*)Ain + (size_t)node * HID + q * 4);
        } else {
            uint2 t = *(const uint2*)((const __half*)Ain + (size_t)node * HID + q * 4);
            float2 a = __half22float2(*(const half2*)&t.x);
            float2 b = __half22float2(*(const half2*)&t.y);
            return make_float4(a.x, a.y, b.x, b.y);
        }
    };
    auto do_prefetch = [&](int tile) {
        int nodebase = tile * 128;
        #pragma unroll
        for (int i = 0; i < 8; i++) {
            int idx = tid + i * 512;
            int r = idx >> 5, q = idx & 31;
            int node = nodebase + r;
            pf[i] = (node < NN) ? load4(node, q) : make_float4(0.f, 0.f, 0.f, 0.f);
        }
    };

    int t0 = blockIdx.x;
    if (t0 < NTILES) do_prefetch(t0);

    for (int tile = t0; tile < NTILES; tile += gridDim.x) {
        int nodebase = tile * 128;
        __syncthreads();   // previous tile's compute done reading A smem

        // ---- split prefetched registers into smem hi/lo ----
        #pragma unroll
        for (int i = 0; i < 8; i++) {
            int idx = tid + i * 512;
            int r = idx >> 5, q = idx & 31;
            uint32_t l01, l23;
            uint32_t h01 = bfsplit2(pf[i].x, pf[i].y, l01);
            uint32_t h23 = bfsplit2(pf[i].z, pf[i].w, l23);
            uint32_t a = swaddr(sb, r, q >> 1) + (q & 1) * 8;
            *(uint2*)(sm + (a - sb) + OFF_AH) = make_uint2(h01, h23);
            *(uint2*)(sm + (a - sb) + OFF_AL) = make_uint2(l01, l23);
        }
        __syncthreads();

        // ---- issue next tile's LDGs; they retire under the MMAs below ----
        int nxt = tile + gridDim.x;
        if (nxt < NTILES) do_prefetch(nxt);

        // ---- compute: 8 k-steps, 3-way split, fp32 acc ----
        float acc[2][4][4];
        #pragma unroll
        for (int i = 0; i < 2; i++)
            #pragma unroll
            for (int j = 0; j < 4; j++)
                #pragma unroll
                for (int e = 0; e < 4; e++) acc[i][j][e] = 0.f;

        #pragma unroll
        for (int ks = 0; ks < 8; ks++) {
            int ch = ks * 2 + lhalf;
            uint32_t Ah[2][4], Al[2][4], Bh[4][2], Bl[4][2], tb[4];
            ldm_x4(Ah[0], swaddr(sb + OFF_AH, mrow,      ch));
            ldm_x4(Ah[1], swaddr(sb + OFF_AH, mrow + 16, ch));
            ldm_x4(Al[0], swaddr(sb + OFF_AL, mrow,      ch));
            ldm_x4(Al[1], swaddr(sb + OFF_AL, mrow + 16, ch));
            ldm_x4(tb, swaddr(sb + OFF_WH, nrow, ch));
            Bh[0][0] = tb[0]; Bh[0][1] = tb[2]; Bh[1][0] = tb[1]; Bh[1][1] = tb[3];
            ldm_x4(tb, swaddr(sb + OFF_WH, nrow + 16, ch));
            Bh[2][0] = tb[0]; Bh[2][1] = tb[2]; Bh[3][0] = tb[1]; Bh[3][1] = tb[3];
            ldm_x4(tb, swaddr(sb + OFF_WL, nrow, ch));
            Bl[0][0] = tb[0]; Bl[0][1] = tb[2]; Bl[1][0] = tb[1]; Bl[1][1] = tb[3];
            ldm_x4(tb, swaddr(sb + OFF_WL, nrow + 16, ch));
            Bl[2][0] = tb[0]; Bl[2][1] = tb[2]; Bl[3][0] = tb[1]; Bl[3][1] = tb[3];

            #pragma unroll
            for (int mi = 0; mi < 2; mi++)
                #pragma unroll
                for (int nf = 0; nf < 4; nf++) {
                    mma16816(acc[mi][nf], Ah[mi], Bh[nf]);
                    mma16816(acc[mi][nf], Al[mi], Bh[nf]);
                    mma16816(acc[mi][nf], Ah[mi], Bl[nf]);
                }
        }

        // ---- epilogue ----
        #pragma unroll
        for (int mi = 0; mi < 2; mi++) {
            int row0 = nodebase + wm * 32 + mi * 16 + g8;
            #pragma unroll
            for (int nf = 0; nf < 4; nf++) {
                int cg = by * 128 + wn * 32 + nf * 8 + 2 * t4;
                if constexpr (EPI == 0) {
                    bool isv = cg >= NH;
                    int c = isv ? cg - NH : cg;
                    float s0 = sSC[c], s1 = sSC[c + 1];
                    float a0 = isv ? sSH[c] : 0.f, a1 = isv ? sSH[c + 1] : 0.f;
                    __half* dp = (isv ? (__half*)vout_ : uout) + c;
                    if (row0 < NN)
                        *(half2*)(dp + (size_t)row0 * NH) =
                            __floats2half2_rn(acc[mi][nf][0] * s0 + a0, acc[mi][nf][1] * s1 + a1);
                    if (row0 + 8 < NN)
                        *(half2*)(dp + (size_t)(row0 + 8) * NH) =
                            __floats2half2_rn(acc[mi][nf][2] * s0 + a0, acc[mi][nf][3] * s1 + a1);
                } else {
                    if (cg < NH) {
                        __half* dp = uout + cg;
                        if (row0 < NN)
                            *(half2*)(dp + (size_t)row0 * NH) =
                                __floats2half2_rn(acc[mi][nf][0], acc[mi][nf][1]);
                        if (row0 + 8 < NN)
                            *(half2*)(dp + (size_t)(row0 + 8) * NH) =
                                __floats2half2_rn(acc[mi][nf][2], acc[mi][nf][3]);
                    } else {
                        int c = cg - NH;
                        float b0 = bias[c], b1 = bias[c + 1];
                        float* dp = (float*)vout_ + c;
                        if (row0 < NN)
                            *(float2*)(dp + (size_t)row0 * NH) =
                                make_float2(acc[mi][nf][0] + b0, acc[mi][nf][1] + b1);
                        if (row0 + 8 < NN)
                            *(float2*)(dp + (size_t)(row0 + 8) * NH) =
                                make_float2(acc[mi][nf][2] + b0, acc[mi][nf][3] + b1);
                    }
                }
            }
        }
    }
}

// ---------------- mean-aggregate + ReLU (layers 1,2; BN pre-folded in GEMM) ----------------
// h = relu(mean(u') + v'), all fp16 in/out.
__global__ void k_agg_bn(const __half* __restrict__ u, const __half* __restrict__ vp,
                         __half* __restrict__ hout)
{
    int gw = (blockIdx.x * blockDim.x + threadIdx.x) >> 5;
    int lane = threadIdx.x & 31;
    if (gw >= NN) return;
    int s0 = g_rowptr[gw], s1 = g_rowptr[gw + 1];
    const uint2* ub = (const uint2*)u;   // row stride = 32 uint2
    float4 acc = make_float4(0.f, 0.f, 0.f, 0.f);
    for (int b = s0; b < s1; b += 32) {
        int cnt = s1 - b; if (cnt > 32) cnt = 32;
        int idxv = (lane < cnt) ? g_col[b + lane] : 0;
        for (int j = 0; j < cnt; j += 4) {
            uint2 t[4]; float p[4];
            #pragma unroll
            for (int q = 0; q < 4; q++) {
                int jq = j + q;
                int s = __shfl_sync(~0u, idxv, jq & 31);
                bool valid = jq < cnt;
                p[q] = valid ? 1.f : 0.f;
                t[q] = ub[(size_t)(valid ? s : 0) * 32 + lane];
            }
            #pragma unroll
            for (int q = 0; q < 4; q++) {
                float2 f0 = __half22float2(*(const half2*)&t[q].x);
                float2 f1 = __half22float2(*(const half2*)&t[q].y);
                acc.x = fmaf(p[q], f0.x, acc.x);
                acc.y = fmaf(p[q], f0.y, acc.y);
                acc.z = fmaf(p[q], f1.x, acc.z);
                acc.w = fmaf(p[q], f1.y, acc.w);
            }
        }
    }
    float iv = g_invdeg[gw];
    uint2 vv = ((const uint2*)vp)[(size_t)gw * 32 + lane];
    float2 v0 = __half22float2(*(const half2*)&vv.x);
    float2 v1 = __half22float2(*(const half2*)&vv.y);
    float o0 = fmaxf(acc.x * iv + v0.x, 0.f);
    float o1 = fmaxf(acc.y * iv + v0.y, 0.f);
    float o2 = fmaxf(acc.z * iv + v1.x, 0.f);
    float o3 = fmaxf(acc.w * iv + v1.y, 0.f);
    uint2 st;
    *(half2*)&st.x = __floats2half2_rn(o0, o1);
    *(half2*)&st.y = __floats2half2_rn(o2, o3);
    ((uint2*)hout)[(size_t)gw * 32 + lane] = st;
}

// ---------------- layer 3: mean-aggregate(p fp16) + v'(has b3), log_softmax ----------------
__global__ void k_agg_lsm(const __half* __restrict__ p, const float* __restrict__ r,
                          float* __restrict__ out)
{
    int gw = (blockIdx.x * blockDim.x + threadIdx.x) >> 5;
    int lane = threadIdx.x & 31;
    if (gw >= NN) return;
    int s0 = g_rowptr[gw], s1 = g_rowptr[gw + 1];
    const uint32_t* pb = (const uint32_t*)p;  // row stride = 32 uint32 (64 halves)
    float ax = 0.f, ay = 0.f;
    for (int b = s0; b < s1; b += 32) {
        int cnt = s1 - b; if (cnt > 32) cnt = 32;
        int idxv = (lane < cnt) ? g_col[b + lane] : 0;
        for (int j = 0; j < cnt; j += 4) {
            uint32_t t[4]; float pw[4];
            #pragma unroll
            for (int q = 0; q < 4; q++) {
                int jq = j + q;
                int s = __shfl_sync(~0u, idxv, jq & 31);
                bool valid = jq < cnt;
                pw[q] = valid ? 1.f : 0.f;
                t[q] = pb[(size_t)(valid ? s : 0) * 32 + lane];
            }
            #pragma unroll
            for (int q = 0; q < 4; q++) {
                float2 f = __half22float2(*(const half2*)&t[q]);
                ax = fmaf(pw[q], f.x, ax);
                ay = fmaf(pw[q], f.y, ay);
            }
        }
    }
    float iv = g_invdeg[gw];
    float2 rr = *(const float2*)(r + (size_t)gw * OUTC + lane * 2);
    float l0 = ax * iv + rr.x;
    float l1 = ay * iv + rr.y;
    float m = fmaxf(l0, l1);
    #pragma unroll
    for (int o = 16; o; o >>= 1) m = fmaxf(m, __shfl_xor_sync(~0u, m, o));
    float s = expf(l0 - m) + expf(l1 - m);
    #pragma unroll
    for (int o = 16; o; o >>= 1) s += __shfl_xor_sync(~0u, s, o);
    float lse = m + logf(s);
    float2 o2; o2.x = l0 - lse; o2.y = l1 - lse;
    *(float2*)(out + (size_t)gw * OUTC + lane * 2) = o2;
}

// ---------------- launch ----------------
extern "C" void kernel_launch(void* const* d_in, const int* in_sizes, int n_in,
                              void* d_out, int out_size)
{
    const float* x   = (const float*)d_in[0];
    const int*   src = (const int*)d_in[1];
    const int*   dst = (const int*)d_in[2];
    const float* W1l = (const float*)d_in[3];
    const float* W1r = (const float*)d_in[4];
    const float* b1  = (const float*)d_in[5];
    const float* g1  = (const float*)d_in[6];
    const float* be1 = (const float*)d_in[7];
    const float* rm1 = (const float*)d_in[8];
    const float* rv1 = (const float*)d_in[9];
    const float* W2l = (const float*)d_in[10];
    const float* W2r = (const float*)d_in[11];
    const float* b2  = (const float*)d_in[12];
    const float* g2  = (const float*)d_in[13];
    const float* be2 = (const float*)d_in[14];
    const float* rm2 = (const float*)d_in[15];
    const float* rv2 = (const float*)d_in[16];
    const float* W3l = (const float*)d_in[17];
    const float* W3r = (const float*)d_in[18];
    const float* b3  = (const float*)d_in[19];
    float* out = (float*)d_out;

    __half* u; float* vf; float* hf;
    cudaGetSymbolAddress((void**)&u,  g_u);
    cudaGetSymbolAddress((void**)&vf, g_v);
    cudaGetSymbolAddress((void**)&hf, g_h);
    __half* vh = (__half*)vf;   // fp16 view for layers 1/2
    __half* hh = (__half*)hf;   // fp16 activations

    static cudaStream_t s2 = nullptr;
    static cudaEvent_t ev_fork = nullptr, ev_join = nullptr;
    if (!s2) {
        cudaStreamCreateWithFlags(&s2, cudaStreamNonBlocking);
        cudaEventCreateWithFlags(&ev_fork, cudaEventDisableTiming);
        cudaEventCreateWithFlags(&ev_join, cudaEventDisableTiming);
    }

    const int NB = (NN + 1023) >> 10;
    const int SMEM = 132096;
    cudaFuncSetAttribute(k_mma_gemm<256, 0, float>,  cudaFuncAttributeMaxDynamicSharedMemorySize, SMEM);
    cudaFuncSetAttribute(k_mma_gemm<256, 0, __half>, cudaFuncAttributeMaxDynamicSharedMemorySize, SMEM);
    cudaFuncSetAttribute(k_mma_gemm<128, 1, __half>, cudaFuncAttributeMaxDynamicSharedMemorySize, SMEM);

    const int AGG_BLOCKS = (NN * 32 + 255) / 256;

    // ---- fork: CSR build on s2, layer-1 GEMM on main stream, join before agg ----
    cudaEventRecord(ev_fork, 0);
    cudaStreamWaitEvent(s2, ev_fork, 0);
    k_zero_deg<<<(NN + 255) / 256, 256, 0, s2>>>();
    k_count<<<(EE + 255) / 256, 256, 0, s2>>>(dst);
    k_scan_block<<<NB, 1024, 0, s2>>>();
    k_scan_tot<<<1, 128, 0, s2>>>(NB);
    k_finalize<<<(NN + 255) / 256, 256, 0, s2>>>();
    k_fill<<<(EE + 255) / 256, 256, 0, s2>>>(src, dst);
    cudaEventRecord(ev_join, s2);

    // Layer 1: GEMM (BN folded) overlaps CSR build
    k_mma_gemm<256, 0, float><<<dim3(74, 2), 512, SMEM>>>(
        x, W1l, W1r, b1, g1, be1, rm1, rv1, u, vh);
    cudaStreamWaitEvent(0, ev_join, 0);
    k_agg_bn<<<AGG_BLOCKS, 256>>>(u, vh, hh);
    // Layer 2
    k_mma_gemm<256, 0, __half><<<dim3(74, 2), 512, SMEM>>>(
        hh, W2l, W2r, b2, g2, be2, rm2, rv2, u, vh);
    k_agg_bn<<<AGG_BLOCKS, 256>>>(u, vh, hh);
    // Layer 3: b3 folded into v'; aggregate + log_softmax
    k_mma_gemm<128, 1, __half><<<dim3(148, 1), 512, SMEM>>>(
        hh, W3l, W3r, b3, nullptr, nullptr, nullptr, nullptr, u, vf);
    k_agg_lsm<<<AGG_BLOCKS, 256>>>(u, vf, out);
}